// round 7
// baseline (speedup 1.0000x reference)
#include <cuda_runtime.h>
#include <math.h>

#define NQ       16
#define BATCH    256
#define NL       4
#define DIN      512
#define OUTD     10

typedef unsigned long long ull;

// ---------------- scratch ----------------
__device__ ull   g_re[BATCH * 32768];        // 64 MB re pairs (lane = qubit 15)
__device__ ull   g_im[BATCH * 32768];        // 64 MB im pairs
__device__ ull   g_T0u[BATCH * 128];
__device__ float g_T1[BATCH * 256];
__device__ ull   g_Upass[4 * 156];           // 13 bit-gates x 12 consts, per pass
__device__ ull   g_LanePk[4 * 6];            // lane (q15) gate consts per layer
__device__ ull   g_DefPk[4 * 24];            // deferred 2 gates x 12, slot = pass-1
__device__ ull   g_LowRe[4 * 1024], g_LowIm[4 * 1024], g_LowImN[4 * 1024];
__device__ ull   g_HighRe[4 * 64],  g_HighIm[4 * 64],  g_HighImN[4 * 64];
__device__ float g_zpart[BATCH * 4 * 16];

// ---------------- f32x2 helpers ----------------
__device__ __forceinline__ ull pk2(float lo, float hi) {
    ull r; asm("mov.b64 %0, {%1, %2};" : "=l"(r) : "f"(lo), "f"(hi)); return r;
}
__device__ __forceinline__ ull bc2(float v) {
    ull r; asm("mov.b64 %0, {%1, %1};" : "=l"(r) : "f"(v)); return r;
}
__device__ __forceinline__ void up2(ull v, float& lo, float& hi) {
    asm("mov.b64 {%0, %1}, %2;" : "=f"(lo), "=f"(hi) : "l"(v));
}
__device__ __forceinline__ ull f2fma(ull a, ull b, ull c) {
    ull d; asm("fma.rn.f32x2 %0, %1, %2, %3;" : "=l"(d) : "l"(a), "l"(b), "l"(c)); return d;
}
__device__ __forceinline__ ull f2mul(ull a, ull b) {
    ull d; asm("mul.rn.f32x2 %0, %1, %2;" : "=l"(d) : "l"(a), "l"(b)); return d;
}
__device__ __forceinline__ ull swap2(ull v) {
    float lo, hi; up2(v, lo, hi); return pk2(hi, lo);
}
__device__ __forceinline__ int swz(int i) { return i ^ ((i >> 3) & 15); }

// ---------------- prep: encoding, product tables, gate constants ----------------
__global__ void prep_kernel(const float* __restrict__ x,
                            const float* __restrict__ W_enc,
                            const float* __restrict__ b_enc,
                            const float* __restrict__ theta)
{
    __shared__ float partial[256];
    __shared__ float cs[NQ], ss[NQ];
    __shared__ float2 Ush[NL * NQ * 4];

    int b   = blockIdx.x;
    int tid = threadIdx.x;
    int q   = tid & 15;
    int seg = tid >> 4;

    {
        float acc = 0.f;
        const float* xb = x + b * DIN;
        int d0 = seg * 32;
        #pragma unroll 8
        for (int d = d0; d < d0 + 32; d++)
            acc += xb[d] * W_enc[d * NQ + q];
        partial[tid] = acc;
    }
    __syncthreads();
    if (tid < NQ) {
        float s = b_enc[tid];
        #pragma unroll
        for (int g = 0; g < 16; g++) s += partial[g * 16 + tid];
        float ang = tanhf(s) * 3.14159265358979323846f;
        cs[tid] = cosf(0.5f * ang);
        ss[tid] = sinf(0.5f * ang);
    }
    __syncthreads();

    {
        int m = tid;
        float p0 = 1.f, p1 = 1.f;
        #pragma unroll
        for (int k = 0; k < 8; k++) {
            int bit = (m >> k) & 1;
            p0 *= bit ? ss[15 - k] : cs[15 - k];
            p1 *= bit ? ss[7 - k]  : cs[7 - k];
        }
        ((float*)g_T0u)[b * 256 + m] = p0;
        g_T1[b * 256 + m] = p1;
    }

    if (b == 0) {
        if (tid < NL * NQ) {
            int l = tid >> 4, qq = tid & 15;
            const float* th = theta + (l * NQ + qq) * 3;
            float a0 = th[0], a1 = th[1], a2 = th[2];
            float ca = cosf(0.5f * a0), sa = sinf(0.5f * a0);
            float cb = cosf(0.5f * a1), sb = sinf(0.5f * a1);
            float cz = cosf(0.5f * a2), sz = sinf(0.5f * a2);
            float2 em = make_float2(cz, -sz);
            float2 ep = make_float2(cz,  sz);
            float2 r00 = make_float2( cb * em.x,  cb * em.y);
            float2 r01 = make_float2(-sb * ep.x, -sb * ep.y);
            float2 r10 = make_float2( sb * em.x,  sb * em.y);
            float2 r11 = make_float2( cb * ep.x,  cb * ep.y);
            float2 u00 = make_float2(ca * r00.x + sa * r10.y, ca * r00.y - sa * r10.x);
            float2 u01 = make_float2(ca * r01.x + sa * r11.y, ca * r01.y - sa * r11.x);
            float2 u10 = make_float2(sa * r00.y + ca * r10.x, -sa * r00.x + ca * r10.y);
            float2 u11 = make_float2(sa * r01.y + ca * r11.x, -sa * r01.x + ca * r11.y);
            int base = tid * 4;
            Ush[base + 0] = u00; Ush[base + 1] = u01;
            Ush[base + 2] = u10; Ush[base + 3] = u11;
        }
        __syncthreads();

        // bit-gate constants per pass (pass pi, u bit g):
        //  g<=9: qubit 14-g (both coverages); g=10..12: covA(pi even): 14-g; covB: 12-g
        for (int kk = tid; kk < 4 * 156; kk += 256) {
            int pi = kk / 156, rem = kk % 156, g = rem / 12, e = rem % 12;
            int qq = (g <= 9) ? (14 - g) : ((pi & 1) ? (12 - g) : (14 - g));
            int j2 = e / 3, kind = e % 3;
            float2 u = Ush[(pi * 16 + qq) * 4 + j2];
            float v = (kind == 0) ? u.x : ((kind == 1) ? u.y : -u.y);
            g_Upass[kk] = bc2(v);
        }
        // lane gate (qubit 15) per layer
        if (tid < NL) {
            int l = tid;
            float2 u00 = Ush[(l * 16 + 15) * 4 + 0];
            float2 u01 = Ush[(l * 16 + 15) * 4 + 1];
            float2 u10 = Ush[(l * 16 + 15) * 4 + 2];
            float2 u11 = Ush[(l * 16 + 15) * 4 + 3];
            g_LanePk[l * 6 + 0] = pk2(u00.x, u11.x);
            g_LanePk[l * 6 + 1] = pk2(u01.x, u10.x);
            g_LanePk[l * 6 + 2] = pk2(-u00.y, -u11.y);
            g_LanePk[l * 6 + 3] = pk2(-u01.y, -u10.y);
            g_LanePk[l * 6 + 4] = pk2(u00.y, u11.y);
            g_LanePk[l * 6 + 5] = pk2(u01.y, u10.y);
        }
        // deferred gates: slot s (= applying pass - 1) carries layer-s gates:
        //  s even (applying pass covB): [q1 (VB1), q0 (VB2)]
        //  s odd  (applying pass covA): [q4 (VB0), q3 (VB1)]
        for (int kk = tid; kk < 4 * 24; kk += 256) {
            int s = kk / 24, rem = kk % 24, d = rem / 12, e = rem % 12;
            int qq = (s & 1) ? (d == 0 ? 4 : 3) : (d == 0 ? 1 : 0);
            int j2 = e / 3, kind = e % 3;
            float2 u = Ush[(s * 16 + qq) * 4 + j2];
            float v = (kind == 0) ? u.x : ((kind == 1) ? u.y : -u.y);
            g_DefPk[kk] = bc2(v);
        }
    }
}

// ---------------- phase tables: Low (u bits 0..9 + lane), High (u bits 9..12 + tile + lane) ----------------
__global__ void phase_prep(const float* __restrict__ phi)
{
    int gid = blockIdx.x * 1024 + threadIdx.x;
    if (gid < 4096) {
        int l = gid >> 10, u = gid & 1023;
        float A = 0.f;
        #pragma unroll
        for (int k = 1; k <= 9; k++) {
            float sk = 1.f - 2.f * ((u >> k) & 1);
            float sm = 1.f - 2.f * ((u >> (k - 1)) & 1);
            A += __ldg(&phi[l * 16 + 14 - k]) * sk * sm;
        }
        float Bt = __ldg(&phi[l * 16 + 14]) * (1.f - 2.f * (u & 1));
        float a0 = A + Bt, a1 = A - Bt;
        float c0, s0, c1, s1;
        sincosf(0.5f * a0, &s0, &c0);
        sincosf(0.5f * a1, &s1, &c1);
        g_LowRe[gid]  = pk2(c0, c1);
        g_LowIm[gid]  = pk2(-s0, -s1);
        g_LowImN[gid] = pk2(s0, s1);
    } else if (gid < 4096 + 256) {
        int g2 = gid - 4096;
        int l = g2 >> 6, j = g2 & 63, h = j >> 2, tile = j & 3;
        float sh0 = 1.f - 2.f * (h & 1);
        float sh1 = 1.f - 2.f * ((h >> 1) & 1);
        float sh2 = 1.f - 2.f * ((h >> 2) & 1);
        float sh3 = 1.f - 2.f * ((h >> 3) & 1);
        float st0 = 1.f - 2.f * (tile & 1);
        float st1 = 1.f - 2.f * ((tile >> 1) & 1);
        const float* ph = phi + l * 16;
        float D, C;
        if (l & 1) {   // applied in covA pass: tile = qubits (q0=bit1, q1=bit0)
            D = __ldg(&ph[2]) * sh3 * sh2 + __ldg(&ph[3]) * sh2 * sh1 + __ldg(&ph[4]) * sh1 * sh0
              + __ldg(&ph[1]) * st0 * sh3 + __ldg(&ph[0]) * st1 * st0;
            C = __ldg(&ph[15]) * st1;
        } else {       // applied in covB pass: tile = qubits (q3=bit1, q4=bit0)
            D = __ldg(&ph[0]) * sh3 * sh2 + __ldg(&ph[1]) * sh2 * sh1 + __ldg(&ph[2]) * sh1 * st1
              + __ldg(&ph[3]) * st1 * st0 + __ldg(&ph[4]) * st0 * sh0;
            C = __ldg(&ph[15]) * sh3;
        }
        float a0 = D + C, a1 = D - C;
        float c0, s0, c1, s1;
        sincosf(0.5f * a0, &s0, &c0);
        sincosf(0.5f * a1, &s1, &c1);
        g_HighRe[g2]  = pk2(c0, c1);
        g_HighIm[g2]  = pk2(-s0, -s1);
        g_HighImN[g2] = pk2(s0, s1);
    }
}

// ---------------- packed 2x2 gate on 8-value register subcube ----------------
template<int VB>
__device__ __forceinline__ void gate8(ull* ar, ull* ai, const ull* u)
{
    ull u00x = u[0], u00y = u[1],  u00yn = u[2];
    ull u01x = u[3], u01y = u[4],  u01yn = u[5];
    ull u10x = u[6], u10y = u[7],  u10yn = u[8];
    ull u11x = u[9], u11y = u[10], u11yn = u[11];
    #pragma unroll
    for (int m = 0; m < 8; m++) {
        if (m & (1 << VB)) continue;
        int m1 = m | (1 << VB);
        ull axr = ar[m],  axi = ai[m];
        ull bxr = ar[m1], bxi = ai[m1];
        ar[m]  = f2fma(u00x, axr, f2fma(u00yn, axi, f2fma(u01x, bxr, f2mul(u01yn, bxi))));
        ai[m]  = f2fma(u00x, axi, f2fma(u00y,  axr, f2fma(u01x, bxi, f2mul(u01y,  bxr))));
        ar[m1] = f2fma(u10x, axr, f2fma(u10yn, axi, f2fma(u11x, bxr, f2mul(u11yn, bxi))));
        ai[m1] = f2fma(u10x, axi, f2fma(u10y,  axr, f2fma(u11x, bxi, f2mul(u11y,  bxr))));
    }
}

// ---------------- the unified per-layer pass ----------------
extern "C" __global__ void __launch_bounds__(1024, 1)
pass_kernel(int pi)
{
    extern __shared__ ull smem[];
    ull* sre = smem;
    ull* sim = smem + 8192;
    __shared__ ull sU[156];
    __shared__ ull sLane[6];
    __shared__ ull sDef[24];
    __shared__ ull sHR[16], sHI[16], sHIN[16];
    __shared__ float wsum[32][16];

    const int t    = threadIdx.x;
    const int tile = blockIdx.x;
    const int b    = blockIdx.y;
    const int base = b * 32768;
    const bool covB = (pi & 1);
    const bool init = (pi == 0);
    const bool fin  = (pi == 4);

    if (!fin) {
        if (t < 156) sU[t] = g_Upass[pi * 156 + t];
        if (t < 6)   sLane[t] = g_LanePk[pi * 6 + t];
    }
    if (!init) {
        if (t < 24) sDef[t] = g_DefPk[(pi - 1) * 24 + t];
        if (t < 16) {
            sHR[t]  = g_HighRe [(pi - 1) * 64 + t * 4 + tile];
            sHI[t]  = g_HighIm [(pi - 1) * 64 + t * 4 + tile];
            sHIN[t] = g_HighImN[(pi - 1) * 64 + t * 4 + tile];
        }
    }

    // ---- load sweep (+ Low part of D_{pi-1}; commutes with deferred gates) ----
    if (init) {
        const float* T1 = g_T1 + b * 256;
        ull t0v = g_T0u[b * 128 + (t & 127)];
        #pragma unroll
        for (int k = 0; k < 8; k++) {
            int u = k * 1024 + t;
            float t1 = T1[(tile << 6) | (k << 3) | (t >> 7)];
            int s = swz(u);
            sre[s] = f2mul(bc2(t1), t0v);
            sim[s] = 0ull;
        }
    } else {
        ull Lre  = g_LowRe [(pi - 1) * 1024 + t];
        ull Lim  = g_LowIm [(pi - 1) * 1024 + t];
        ull LimN = g_LowImN[(pi - 1) * 1024 + t];
        #pragma unroll
        for (int k = 0; k < 8; k++) {
            int u = k * 1024 + t;
            int p = covB ? ((k << 12) | (tile << 10) | t)
                         : ((tile << 13) | (k << 10) | t);
            ull re = g_re[base + p], im = g_im[base + p];
            int s = swz(u);
            sre[s] = f2fma(Lre, re, f2mul(LimN, im));
            sim[s] = f2fma(Lre, im, f2mul(Lim,  re));
        }
    }
    __syncthreads();

    // ---- R0: u bits 10..12 (deferred gates -> High phase -> layer gates) ----
    {
        ull ar[8], ai[8];
        #pragma unroll
        for (int e = 0; e < 8; e++) {
            int s = swz((e << 10) | t);
            ar[e] = sre[s]; ai[e] = sim[s];
        }
        if (!init) {
            if (covB) { gate8<1>(ar, ai, sDef); gate8<2>(ar, ai, sDef + 12); }
            else      { gate8<0>(ar, ai, sDef); gate8<1>(ar, ai, sDef + 12); }
            int tb9 = (t >> 9) & 1;
            #pragma unroll
            for (int e = 0; e < 8; e++) {
                int h = (e << 1) | tb9;
                ull cr = sHR[h], ci = sHI[h], cin = sHIN[h];
                ull nr = f2fma(cr, ar[e], f2mul(cin, ai[e]));
                ai[e]  = f2fma(cr, ai[e], f2mul(ci,  ar[e]));
                ar[e]  = nr;
            }
        }
        if (!fin) {
            gate8<0>(ar, ai, sU + 10 * 12);
            gate8<1>(ar, ai, sU + 11 * 12);
            gate8<2>(ar, ai, sU + 12 * 12);
            #pragma unroll
            for (int e = 0; e < 8; e++) {
                int s = swz((e << 10) | t);
                sre[s] = ar[e]; sim[s] = ai[e];
            }
        } else {
            // ---- expectations (state is final; no store) ----
            float acc2 = 0.f, acc3 = 0.f, acc4 = 0.f, pt0 = 0.f, pt1 = 0.f;
            #pragma unroll
            for (int e = 0; e < 8; e++) {
                ull pp = f2fma(ar[e], ar[e], f2mul(ai[e], ai[e]));
                float l0, l1; up2(pp, l0, l1);
                pt0 += l0; pt1 += l1;
                float p = l0 + l1;
                acc2 += (e & 4) ? -p : p;   // q2 = u bit 12
                acc3 += (e & 2) ? -p : p;   // q3 = u bit 11
                acc4 += (e & 1) ? -p : p;   // q4 = u bit 10
            }
            float pt = pt0 + pt1;
            float acc[16];
            acc[0] = (tile & 2) ? -pt : pt;   // q0 = p bit 14 = tile bit 1
            acc[1] = (tile & 1) ? -pt : pt;   // q1 = p bit 13 = tile bit 0
            acc[2] = acc2; acc[3] = acc3; acc[4] = acc4;
            #pragma unroll
            for (int q = 5; q < 15; q++)
                acc[q] = ((t >> (14 - q)) & 1) ? -pt : pt;   // q = 14-k <-> t bit k
            acc[15] = pt0 - pt1;
            #pragma unroll
            for (int q = 0; q < 16; q++) {
                float v = acc[q];
                #pragma unroll
                for (int o = 16; o > 0; o >>= 1)
                    v += __shfl_down_sync(0xffffffffu, v, o);
                if ((t & 31) == 0) wsum[t >> 5][q] = v;
            }
            __syncthreads();
            if (t < 16) {
                float v = 0.f;
                #pragma unroll
                for (int w = 0; w < 32; w++) v += wsum[w][t];
                g_zpart[(b * 4 + tile) * 16 + t] = v;
            }
            return;
        }
    }

    // ---- R1: u bits 0,1,2 + lane gate ----
    __syncthreads();
    {
        ull ar[8], ai[8];
        #pragma unroll
        for (int e = 0; e < 8; e++) {
            int s = swz((t << 3) | e);
            ar[e] = sre[s]; ai[e] = sim[s];
        }
        {
            ull P1 = sLane[0], P2 = sLane[1], P3 = sLane[2],
                P4 = sLane[3], P5 = sLane[4], P6 = sLane[5];
            #pragma unroll
            for (int m = 0; m < 8; m++) {
                ull sar = swap2(ar[m]), sai = swap2(ai[m]);
                ull nr = f2fma(P1, ar[m], f2fma(P2, sar, f2fma(P3, ai[m], f2mul(P4, sai))));
                ull ni = f2fma(P1, ai[m], f2fma(P2, sai, f2fma(P5, ar[m], f2mul(P6, sar))));
                ar[m] = nr; ai[m] = ni;
            }
        }
        gate8<0>(ar, ai, sU + 0);
        gate8<1>(ar, ai, sU + 12);
        gate8<2>(ar, ai, sU + 24);
        #pragma unroll
        for (int e = 0; e < 8; e++) {
            int s = swz((t << 3) | e);
            sre[s] = ar[e]; sim[s] = ai[e];
        }
    }

    // ---- R2: u bits 3,4,5 ----
    __syncthreads();
    {
        ull ar[8], ai[8];
        int pre = ((t >> 3) << 6) | (t & 7);
        #pragma unroll
        for (int e = 0; e < 8; e++) {
            int s = swz(pre | (e << 3));
            ar[e] = sre[s]; ai[e] = sim[s];
        }
        gate8<0>(ar, ai, sU + 36);
        gate8<1>(ar, ai, sU + 48);
        gate8<2>(ar, ai, sU + 60);
        #pragma unroll
        for (int e = 0; e < 8; e++) {
            int s = swz(pre | (e << 3));
            sre[s] = ar[e]; sim[s] = ai[e];
        }
    }

    // ---- R3: u bits 6,7,8 ----
    __syncthreads();
    {
        ull ar[8], ai[8];
        int pre = ((t >> 6) << 9) | (t & 63);
        #pragma unroll
        for (int e = 0; e < 8; e++) {
            int s = swz(pre | (e << 6));
            ar[e] = sre[s]; ai[e] = sim[s];
        }
        gate8<0>(ar, ai, sU + 72);
        gate8<1>(ar, ai, sU + 84);
        gate8<2>(ar, ai, sU + 96);
        #pragma unroll
        for (int e = 0; e < 8; e++) {
            int s = swz(pre | (e << 6));
            sre[s] = ar[e]; sim[s] = ai[e];
        }
    }

    // ---- R4: u bit 9 (single gate; pairs over e bit 0) ----
    __syncthreads();
    {
        ull ar[8], ai[8];
        int pre = ((t >> 9) << 10) | (t & 511);
        #pragma unroll
        for (int e = 0; e < 8; e++) {
            int u = ((e >> 1) << 11) | ((e & 1) << 9) | pre;
            int s = swz(u);
            ar[e] = sre[s]; ai[e] = sim[s];
        }
        gate8<0>(ar, ai, sU + 108);
        #pragma unroll
        for (int e = 0; e < 8; e++) {
            int u = ((e >> 1) << 11) | ((e & 1) << 9) | pre;
            int s = swz(u);
            sre[s] = ar[e]; sim[s] = ai[e];
        }
    }

    // ---- store sweep ----
    __syncthreads();
    #pragma unroll
    for (int k = 0; k < 8; k++) {
        int u = k * 1024 + t;
        int p = covB ? ((k << 12) | (tile << 10) | t)
                     : ((tile << 13) | (k << 10) | t);
        int s = swz(u);
        g_re[base + p] = sre[s];
        g_im[base + p] = sim[s];
    }
}

// ---------------- final reduce + MLP ----------------
__global__ void final_kernel(const float* __restrict__ W1, const float* __restrict__ b1,
                             const float* __restrict__ W2, const float* __restrict__ b2,
                             float* __restrict__ out)
{
    int t = threadIdx.x;
    int warp = t >> 5, lane = t & 31;
    int b = blockIdx.x * 8 + warp;

    float z = 0.f;
    if (lane < 16) {
        #pragma unroll
        for (int c = 0; c < 4; c++) z += g_zpart[(b * 4 + c) * 16 + lane];
    }
    float h = b1[lane];
    #pragma unroll
    for (int q = 0; q < 16; q++) {
        float zq = __shfl_sync(0xffffffffu, z, q);
        h += zq * W1[q * 32 + lane];
    }
    h = fmaxf(h, 0.f);

    float o = (lane < OUTD) ? b2[lane] : 0.f;
    #pragma unroll
    for (int j = 0; j < 32; j++) {
        float hj = __shfl_sync(0xffffffffu, h, j);
        if (lane < OUTD) o += hj * W2[j * OUTD + lane];
    }
    if (lane < OUTD) out[b * OUTD + lane] = o;
}

// ---------------- launch ----------------
extern "C" void kernel_launch(void* const* d_in, const int* in_sizes, int n_in,
                              void* d_out, int out_size)
{
    const float* x     = (const float*)d_in[0];
    const float* W_enc = (const float*)d_in[1];
    const float* b_enc = (const float*)d_in[2];
    const float* theta = (const float*)d_in[3];
    const float* phi   = (const float*)d_in[4];
    const float* W1    = (const float*)d_in[5];
    const float* b1    = (const float*)d_in[6];
    const float* W2    = (const float*)d_in[7];
    const float* b2    = (const float*)d_in[8];
    float* out = (float*)d_out;

    cudaFuncSetAttribute((const void*)pass_kernel,
                         cudaFuncAttributeMaxDynamicSharedMemorySize, 131072);

    prep_kernel<<<256, 256>>>(x, W_enc, b_enc, theta);
    phase_prep<<<5, 1024>>>(phi);

    for (int pi = 0; pi < 5; pi++)
        pass_kernel<<<dim3(4, 256), 1024, 131072>>>(pi);

    final_kernel<<<32, 256>>>(W1, b1, W2, b2, out);
}

// round 9
// speedup vs baseline: 1.0818x; 1.0818x over previous
#include <cuda_runtime.h>
#include <math.h>

#define NQ       16
#define BATCH    256
#define NL       4
#define DIN      512
#define OUTD     10

typedef unsigned long long ull;

// ---------------- scratch (SoA state, packed across amp bit 0 = qubit 15) ----------------
__device__ ull   g_re[BATCH * 32768];        // 64 MB re pairs
__device__ ull   g_im[BATCH * 32768];        // 64 MB im pairs
__device__ ull   g_T0u[BATCH * 128];         // product table, amp low-8 bits (float pairs)
__device__ float g_T1[BATCH * 256];          // product table, amp high-8 bits
__device__ ull   g_Upk[NL * 12 * 12];        // broadcast-packed 2x2 gates, qubits 3..14
__device__ ull   g_Lq[NL * 6];               // lane gate (qubit 15) packed consts
__device__ float2 g_M8v[NL * 4 * 64];        // fused 8x8 (qubits 0,1,2) x phase variants [l][s3][s15]
__device__ ull   g_PrRe[NL * 4096], g_PrIm[NL * 4096], g_PrImN[NL * 4096];
__device__ float g_zpart[BATCH * 16 * 16];

// ---------------- f32x2 helpers ----------------
__device__ __forceinline__ ull pk2(float lo, float hi) {
    ull r; asm("mov.b64 %0, {%1, %2};" : "=l"(r) : "f"(lo), "f"(hi)); return r;
}
__device__ __forceinline__ ull bc2(float v) {
    ull r; asm("mov.b64 %0, {%1, %1};" : "=l"(r) : "f"(v)); return r;
}
__device__ __forceinline__ void up2(ull v, float& lo, float& hi) {
    asm("mov.b64 {%0, %1}, %2;" : "=f"(lo), "=f"(hi) : "l"(v));
}
__device__ __forceinline__ ull f2fma(ull a, ull b, ull c) {
    ull d; asm("fma.rn.f32x2 %0, %1, %2, %3;" : "=l"(d) : "l"(a), "l"(b), "l"(c)); return d;
}
__device__ __forceinline__ ull f2mul(ull a, ull b) {
    ull d; asm("mul.rn.f32x2 %0, %1, %2;" : "=l"(d) : "l"(a), "l"(b)); return d;
}
__device__ __forceinline__ ull swap2(ull v) {
    float lo, hi; up2(v, lo, hi); return pk2(hi, lo);
}
__device__ __forceinline__ float2 cmulh(float2 a, float2 b) {
    return make_float2(a.x * b.x - a.y * b.y, a.x * b.y + a.y * b.x);
}
__device__ __forceinline__ int swz(int i) { return i ^ ((i >> 3) & 15); }

// ---------------- prep ----------------
__global__ void prep_kernel(const float* __restrict__ x,
                            const float* __restrict__ W_enc,
                            const float* __restrict__ b_enc,
                            const float* __restrict__ theta,
                            const float* __restrict__ phi)
{
    __shared__ float partial[256];
    __shared__ float cs[NQ], ss[NQ];
    __shared__ float2 Ush[NL * NQ * 4];
    __shared__ float2 sM8[256];

    int b   = blockIdx.x;
    int tid = threadIdx.x;
    int q   = tid & 15;
    int seg = tid >> 4;

    {
        float acc = 0.f;
        const float* xb = x + b * DIN;
        int d0 = seg * 32;
        #pragma unroll 8
        for (int d = d0; d < d0 + 32; d++)
            acc += xb[d] * W_enc[d * NQ + q];
        partial[tid] = acc;
    }
    __syncthreads();
    if (tid < NQ) {
        float s = b_enc[tid];
        #pragma unroll
        for (int g = 0; g < 16; g++) s += partial[g * 16 + tid];
        float ang = tanhf(s) * 3.14159265358979323846f;
        cs[tid] = cosf(0.5f * ang);
        ss[tid] = sinf(0.5f * ang);
    }
    __syncthreads();

    // product tables over amplitude bits (amp bit k -> qubit 15-k)
    {
        int m = tid;
        float p0 = 1.f, p1 = 1.f;
        #pragma unroll
        for (int k = 0; k < 8; k++) {
            int bit = (m >> k) & 1;
            p0 *= bit ? ss[15 - k] : cs[15 - k];
            p1 *= bit ? ss[7 - k]  : cs[7 - k];
        }
        ((float*)g_T0u)[b * 256 + m] = p0;
        g_T1[b * 256 + m] = p1;
    }

    if (b == 0) {
        if (tid < NL * NQ) {
            int l = tid >> 4, qq = tid & 15;
            const float* th = theta + (l * NQ + qq) * 3;
            float a0 = th[0], a1 = th[1], a2 = th[2];
            float ca = cosf(0.5f * a0), sa = sinf(0.5f * a0);
            float cb = cosf(0.5f * a1), sb = sinf(0.5f * a1);
            float cz = cosf(0.5f * a2), sz = sinf(0.5f * a2);
            float2 em = make_float2(cz, -sz);
            float2 ep = make_float2(cz,  sz);
            float2 r00 = make_float2( cb * em.x,  cb * em.y);
            float2 r01 = make_float2(-sb * ep.x, -sb * ep.y);
            float2 r10 = make_float2( sb * em.x,  sb * em.y);
            float2 r11 = make_float2( cb * ep.x,  cb * ep.y);
            float2 u00 = make_float2(ca * r00.x + sa * r10.y, ca * r00.y - sa * r10.x);
            float2 u01 = make_float2(ca * r01.x + sa * r11.y, ca * r01.y - sa * r11.x);
            float2 u10 = make_float2(sa * r00.y + ca * r10.x, -sa * r00.x + ca * r10.y);
            float2 u11 = make_float2(sa * r01.y + ca * r11.x, -sa * r01.x + ca * r11.y);
            int base = tid * 4;
            Ush[base + 0] = u00; Ush[base + 1] = u01;
            Ush[base + 2] = u10; Ush[base + 3] = u11;
        }
        __syncthreads();

        // broadcast-packed passA gate constants for qubits 3..14 (g = qubit-3)
        for (int k = tid; k < NL * 144; k += 256) {
            int l = k / 144, rem = k % 144, g = rem / 12, e = rem % 12;
            int j2 = e / 3, kind = e % 3;
            float2 u = Ush[(l * 16 + (g + 3)) * 4 + j2];
            float v = (kind == 0) ? u.x : ((kind == 1) ? u.y : -u.y);
            g_Upk[k] = bc2(v);
        }

        // lane gate (qubit 15) packed constants
        if (tid < NL) {
            int l = tid;
            float2 u00 = Ush[(l * 16 + 15) * 4 + 0];
            float2 u01 = Ush[(l * 16 + 15) * 4 + 1];
            float2 u10 = Ush[(l * 16 + 15) * 4 + 2];
            float2 u11 = Ush[(l * 16 + 15) * 4 + 3];
            g_Lq[l * 6 + 0] = pk2(u00.x, u11.x);
            g_Lq[l * 6 + 1] = pk2(u01.x, u10.x);
            g_Lq[l * 6 + 2] = pk2(-u00.y, -u11.y);
            g_Lq[l * 6 + 3] = pk2(-u01.y, -u10.y);
            g_Lq[l * 6 + 4] = pk2(u00.y, u11.y);
            g_Lq[l * 6 + 5] = pk2(u01.y, u10.y);
        }

        // base fused 8x8 for qubits 0,1,2  (j bit2=q0, bit1=q1, bit0=q2)
        {
            int l = tid >> 6, rem = tid & 63, j = rem >> 3, jp = rem & 7;
            float2 A = Ush[(l * 16 + 0) * 4 + ((j >> 2) & 1) * 2 + ((jp >> 2) & 1)];
            float2 B = Ush[(l * 16 + 1) * 4 + ((j >> 1) & 1) * 2 + ((jp >> 1) & 1)];
            float2 C = Ush[(l * 16 + 2) * 4 + ((j      ) & 1) * 2 + ((jp      ) & 1)];
            sM8[tid] = cmulh(cmulh(A, B), C);
        }
        __syncthreads();
        // fold phase edges (0,1),(1,2),(2,3),(15,0) into 4 variants (s3 = qubit-3 spin, s15 = lane)
        {
            int l = tid >> 6, rem = tid & 63, j = rem >> 3;
            float s0  = 1.f - 2.f * ((j >> 2) & 1);
            float s1  = 1.f - 2.f * ((j >> 1) & 1);
            float s2c = 1.f - 2.f * (j & 1);
            float p0 = phi[l * 16 + 0], p1 = phi[l * 16 + 1];
            float p2 = phi[l * 16 + 2], p15 = phi[l * 16 + 15];
            float angj = p0 * s0 * s1 + p1 * s1 * s2c;
            float2 m = sM8[tid];
            #pragma unroll
            for (int s3i = 0; s3i < 2; s3i++)
            #pragma unroll
            for (int s15i = 0; s15i < 2; s15i++) {
                float s3  = 1.f - 2.f * s3i;
                float s15 = 1.f - 2.f * s15i;
                float ang = angj + p2 * s2c * s3 + p15 * s15 * s0;
                float c, s;
                sincosf(0.5f * ang, &s, &c);
                float2 F = make_float2(c, -s);
                g_M8v[((l * 2 + s3i) * 2 + s15i) * 64 + rem] = cmulh(F, m);
            }
        }
    }
}

// ---------------- Pr tables: ZZ edges (3,4)..(13,14) + lane-split edge (14,15) ----------------
__global__ void pr_kernel(const float* __restrict__ phi)
{
    int gid = blockIdx.x * blockDim.x + threadIdx.x;   // NL*4096
    int l = gid >> 12;
    int p = gid & 4095;
    float ang = 0.f;
    #pragma unroll
    for (int bb = 0; bb < 11; bb++) {
        float sA = 1.f - 2.f * ((p >> (bb + 1)) & 1);
        float sB = 1.f - 2.f * ((p >> bb) & 1);
        ang += __ldg(&phi[l * 16 + 13 - bb]) * sA * sB;   // edge (13-bb, 14-bb)
    }
    float e14 = __ldg(&phi[l * 16 + 14]) * (1.f - 2.f * (p & 1));  // edge (14,15)
    float a0 = ang + e14, a1 = ang - e14;
    float c0, s0, c1, s1;
    sincosf(0.5f * a0, &s0, &c0);
    sincosf(0.5f * a1, &s1, &c1);
    g_PrRe[l * 4096 + p]  = pk2(c0, c1);
    g_PrIm[l * 4096 + p]  = pk2(-s0, -s1);
    g_PrImN[l * 4096 + p] = pk2(s0, s1);
}

// ---------------- packed 2x2 gate on 8-value register subcube ----------------
template<int VB>
__device__ __forceinline__ void gate8(ull* ar, ull* ai, const ull* u)
{
    ull u00x = u[0], u00y = u[1],  u00yn = u[2];
    ull u01x = u[3], u01y = u[4],  u01yn = u[5];
    ull u10x = u[6], u10y = u[7],  u10yn = u[8];
    ull u11x = u[9], u11y = u[10], u11yn = u[11];
    #pragma unroll
    for (int m = 0; m < 8; m++) {
        if (m & (1 << VB)) continue;
        int m1 = m | (1 << VB);
        ull axr = ar[m],  axi = ai[m];
        ull bxr = ar[m1], bxi = ai[m1];
        ar[m]  = f2fma(u00x, axr, f2fma(u00yn, axi, f2fma(u01x, bxr, f2mul(u01yn, bxi))));
        ai[m]  = f2fma(u00x, axi, f2fma(u00y,  axr, f2fma(u01x, bxi, f2mul(u01y,  bxr))));
        ar[m1] = f2fma(u10x, axr, f2fma(u10yn, axi, f2fma(u11x, bxr, f2mul(u11yn, bxi))));
        ai[m1] = f2fma(u10x, axi, f2fma(u10y,  axr, f2fma(u11x, bxi, f2mul(u11y,  bxr))));
    }
}

// ---------------- PassA: lane gate (q15) + 12 gates (q3..14); 4096-pair blocks, 2 CTAs/SM ----------------
extern "C" __global__ void __launch_bounds__(512, 2)
passA_kernel(int layer, int init)
{
    extern __shared__ ull smem[];
    ull* sre = smem;           // 4096
    ull* sim = smem + 4096;    // 4096
    __shared__ ull sU[144];
    __shared__ ull sLq[6];

    int t    = threadIdx.x;
    int tile = blockIdx.x;     // p bits 12..14 (qubits 2,1,0) — untouched in passA
    int b    = blockIdx.y;
    int base = b * 32768 + tile * 4096;

    if (t < 144) sU[t] = g_Upk[layer * 144 + t];
    if (t < 6)   sLq[t] = g_Lq[layer * 6 + t];

    if (init) {
        #pragma unroll
        for (int k = 0; k < 8; k++) {
            int u = k * 512 + t;
            int p = (tile << 12) | u;
            float t1 = g_T1[b * 256 + (p >> 7)];
            ull  t0 = g_T0u[b * 128 + (p & 127)];
            int s = swz(u);
            sre[s] = f2mul(bc2(t1), t0);
            sim[s] = 0ull;
        }
    } else {
        #pragma unroll
        for (int k = 0; k < 8; k++) {
            int u = k * 512 + t;
            int s = swz(u);
            sre[s] = g_re[base + u];
            sim[s] = g_im[base + u];
        }
    }

    #pragma unroll
    for (int rr = 0; rr < 4; rr++) {
        __syncthreads();
        ull ar[8], ai[8];
        int s  = 3 * rr;
        int lo = t & ((1 << s) - 1);
        int hi = t >> s;
        int pre = (hi << (s + 3)) | lo;
        int idxs[8];
        #pragma unroll
        for (int j = 0; j < 8; j++) idxs[j] = pre | (j << s);

        #pragma unroll
        for (int j = 0; j < 8; j++) {
            int sp = swz(idxs[j]);
            ar[j] = sre[sp];
            ai[j] = sim[sp];
        }

        if (rr == 0) {
            // lane gate: qubit 15 (packing lane)
            ull P1 = sLq[0], P2 = sLq[1], P3 = sLq[2], P4 = sLq[3], P5 = sLq[4], P6 = sLq[5];
            #pragma unroll
            for (int m = 0; m < 8; m++) {
                ull sar = swap2(ar[m]), sai = swap2(ai[m]);
                ull nr = f2fma(P1, ar[m], f2fma(P2, sar, f2fma(P3, ai[m], f2mul(P4, sai))));
                ull ni = f2fma(P1, ai[m], f2fma(P2, sai, f2fma(P5, ar[m], f2mul(P6, sar))));
                ar[m] = nr; ai[m] = ni;
            }
        }

        // gates on u bits 3rr, 3rr+1, 3rr+2  (u bit k <-> qubit 14-k; const idx g = 11-k)
        gate8<0>(ar, ai, &sU[(11 - 3 * rr) * 12]);
        gate8<1>(ar, ai, &sU[(10 - 3 * rr) * 12]);
        gate8<2>(ar, ai, &sU[( 9 - 3 * rr) * 12]);

        #pragma unroll
        for (int j = 0; j < 8; j++) {
            int sp = swz(idxs[j]);
            sre[sp] = ar[j];
            sim[sp] = ai[j];
        }
    }
    __syncthreads();

    // epilogue: Pr phase + writeout (Pr indexed by u = p bits 0..11)
    const ull* PR  = g_PrRe  + layer * 4096;
    const ull* PI  = g_PrIm  + layer * 4096;
    const ull* PIN = g_PrImN + layer * 4096;
    #pragma unroll
    for (int k = 0; k < 8; k++) {
        int u = k * 512 + t;
        int s = swz(u);
        ull re = sre[s], im = sim[s];
        ull cr = PR[u], ci = PI[u], cin = PIN[u];
        ull nre = f2fma(cr, re, f2mul(cin, im));
        ull nim = f2fma(cr, im, f2mul(ci, re));
        g_re[base + u] = nre;
        g_im[base + u] = nim;
    }
}

// ---------------- PassB: 8x8 gate on qubits 0,1,2 (+ folded phases, + expectations) ----------------
extern "C" __global__ void __launch_bounds__(256)
passB_kernel(int layer, int last)
{
    __shared__ ull PX[2][64], PY[2][64], PNY[2][64];
    __shared__ float wsum[8][16];

    int t = threadIdx.x;
    int b = blockIdx.y;

    if (t < 128) {
        int s3 = t >> 6, k = t & 63;
        float2 m0 = g_M8v[((layer * 2 + s3) * 2 + 0) * 64 + k];   // lane 0: s15=+1
        float2 m1 = g_M8v[((layer * 2 + s3) * 2 + 1) * 64 + k];   // lane 1: s15=-1
        PX[s3][k]  = pk2(m0.x, m1.x);
        PY[s3][k]  = pk2(m0.y, m1.y);
        PNY[s3][k] = pk2(-m0.y, -m1.y);
    }
    __syncthreads();

    int r  = blockIdx.x * 256 + t;     // p bits 0..11
    int s3 = (r >> 11) & 1;            // qubit-3 spin variant
    int gb = b * 32768;

    ull are[8], aim[8];
    #pragma unroll
    for (int jp = 0; jp < 8; jp++) {
        are[jp] = g_re[gb + jp * 4096 + r];
        aim[jp] = g_im[gb + jp * 4096 + r];
    }

    ull ore[8], oim[8];
    #pragma unroll
    for (int j = 0; j < 8; j++) {
        ull mx0 = PX[s3][j * 8], my0 = PY[s3][j * 8], nmy0 = PNY[s3][j * 8];
        ull orr = f2fma(nmy0, aim[0], f2mul(mx0, are[0]));
        ull oi  = f2fma(my0,  are[0], f2mul(mx0, aim[0]));
        #pragma unroll
        for (int jp = 1; jp < 8; jp++) {
            ull mx = PX[s3][j * 8 + jp], my = PY[s3][j * 8 + jp], nmy = PNY[s3][j * 8 + jp];
            orr = f2fma(mx, are[jp], orr);
            orr = f2fma(nmy, aim[jp], orr);
            oi  = f2fma(mx, aim[jp], oi);
            oi  = f2fma(my, are[jp], oi);
        }
        ore[j] = orr;
        oim[j] = oi;
    }

    if (!last) {
        #pragma unroll
        for (int j = 0; j < 8; j++) {
            g_re[gb + j * 4096 + r] = ore[j];
            g_im[gb + j * 4096 + r] = oim[j];
        }
    } else {
        float ptl0 = 0.f, ptl1 = 0.f, a0 = 0.f, a1 = 0.f, a2 = 0.f;
        #pragma unroll
        for (int j = 0; j < 8; j++) {
            ull pp = f2fma(ore[j], ore[j], f2mul(oim[j], oim[j]));
            float l0, l1; up2(pp, l0, l1);
            float pj = l0 + l1;
            ptl0 += l0; ptl1 += l1;
            a0 += ((j >> 2) & 1) ? -pj : pj;
            a1 += ((j >> 1) & 1) ? -pj : pj;
            a2 += ( j       & 1) ? -pj : pj;
        }
        float pt = ptl0 + ptl1;
        float acc[16];
        acc[0] = a0; acc[1] = a1; acc[2] = a2;
        #pragma unroll
        for (int q = 3; q < 15; q++)
            acc[q] = ((r >> (14 - q)) & 1) ? -pt : pt;
        acc[15] = ptl0 - ptl1;

        #pragma unroll
        for (int q = 0; q < 16; q++) {
            float v = acc[q];
            #pragma unroll
            for (int ofs = 16; ofs > 0; ofs >>= 1)
                v += __shfl_down_sync(0xffffffffu, v, ofs);
            if ((t & 31) == 0) wsum[t >> 5][q] = v;
        }
        __syncthreads();
        if (t < 16) {
            float v = 0.f;
            #pragma unroll
            for (int w = 0; w < 8; w++) v += wsum[w][t];
            g_zpart[(b * 16 + blockIdx.x) * 16 + t] = v;
        }
    }
}

// ---------------- final reduce + MLP ----------------
__global__ void final_kernel(const float* __restrict__ W1, const float* __restrict__ b1,
                             const float* __restrict__ W2, const float* __restrict__ b2,
                             float* __restrict__ out)
{
    int t = threadIdx.x;
    int warp = t >> 5, lane = t & 31;
    int b = blockIdx.x * 8 + warp;

    float z = 0.f;
    if (lane < 16) {
        #pragma unroll
        for (int c = 0; c < 16; c++) z += g_zpart[(b * 16 + c) * 16 + lane];
    }
    float h = b1[lane];
    #pragma unroll
    for (int q = 0; q < 16; q++) {
        float zq = __shfl_sync(0xffffffffu, z, q);
        h += zq * W1[q * 32 + lane];
    }
    h = fmaxf(h, 0.f);

    float o = (lane < OUTD) ? b2[lane] : 0.f;
    #pragma unroll
    for (int j = 0; j < 32; j++) {
        float hj = __shfl_sync(0xffffffffu, h, j);
        if (lane < OUTD) o += hj * W2[j * OUTD + lane];
    }
    if (lane < OUTD) out[b * OUTD + lane] = o;
}

// ---------------- launch ----------------
extern "C" void kernel_launch(void* const* d_in, const int* in_sizes, int n_in,
                              void* d_out, int out_size)
{
    const float* x     = (const float*)d_in[0];
    const float* W_enc = (const float*)d_in[1];
    const float* b_enc = (const float*)d_in[2];
    const float* theta = (const float*)d_in[3];
    const float* phi   = (const float*)d_in[4];
    const float* W1    = (const float*)d_in[5];
    const float* b1    = (const float*)d_in[6];
    const float* W2    = (const float*)d_in[7];
    const float* b2    = (const float*)d_in[8];
    float* out = (float*)d_out;

    cudaFuncSetAttribute((const void*)passA_kernel,
                         cudaFuncAttributeMaxDynamicSharedMemorySize, 65536);

    prep_kernel<<<256, 256>>>(x, W_enc, b_enc, theta, phi);
    pr_kernel<<<16, 1024>>>(phi);

    for (int l = 0; l < NL; l++) {
        passA_kernel<<<dim3(8, 256), 512, 65536>>>(l, l == 0 ? 1 : 0);
        passB_kernel<<<dim3(16, 256), 256>>>(l, l == NL - 1 ? 1 : 0);
    }

    final_kernel<<<32, 256>>>(W1, b1, W2, b2, out);
}

// round 10
// speedup vs baseline: 1.1270x; 1.0418x over previous
#include <cuda_runtime.h>
#include <math.h>

#define NQ       16
#define BATCH    256
#define NL       4
#define DIN      512
#define OUTD     10

typedef unsigned long long ull;

// ---------------- scratch (SoA state, packed across amp bit 0 = qubit 15) ----------------
__device__ ull   g_re[BATCH * 32768];        // 64 MB re pairs
__device__ ull   g_im[BATCH * 32768];        // 64 MB im pairs
__device__ ull   g_T0u[BATCH * 128];         // product table, amp low-8 bits (float pairs)
__device__ float g_T1[BATCH * 256];          // product table, amp high-8 bits
__device__ ull   g_Upk[NL * 12 * 12];        // broadcast-packed 2x2 gates, qubits 3..14
__device__ ull   g_Lq[NL * 6];               // lane gate (qubit 15) packed consts
__device__ ull   g_Bpk[NL * 36];             // broadcast-packed gates q0,q1,q2
__device__ ull   g_DjRe[NL * 16], g_DjIm[NL * 16], g_DjImN[NL * 16];  // diag phase [l][s3][j]
__device__ ull   g_PrRe[NL * 4096], g_PrIm[NL * 4096], g_PrImN[NL * 4096];
__device__ float g_zpart[BATCH * 16 * 16];

// ---------------- f32x2 helpers ----------------
__device__ __forceinline__ ull pk2(float lo, float hi) {
    ull r; asm("mov.b64 %0, {%1, %2};" : "=l"(r) : "f"(lo), "f"(hi)); return r;
}
__device__ __forceinline__ ull bc2(float v) {
    ull r; asm("mov.b64 %0, {%1, %1};" : "=l"(r) : "f"(v)); return r;
}
__device__ __forceinline__ void up2(ull v, float& lo, float& hi) {
    asm("mov.b64 {%0, %1}, %2;" : "=f"(lo), "=f"(hi) : "l"(v));
}
__device__ __forceinline__ ull f2fma(ull a, ull b, ull c) {
    ull d; asm("fma.rn.f32x2 %0, %1, %2, %3;" : "=l"(d) : "l"(a), "l"(b), "l"(c)); return d;
}
__device__ __forceinline__ ull f2mul(ull a, ull b) {
    ull d; asm("mul.rn.f32x2 %0, %1, %2;" : "=l"(d) : "l"(a), "l"(b)); return d;
}
__device__ __forceinline__ ull swap2(ull v) {
    float lo, hi; up2(v, lo, hi); return pk2(hi, lo);
}
__device__ __forceinline__ int swz(int i) { return i ^ ((i >> 3) & 15); }

// ---------------- prep ----------------
__global__ void prep_kernel(const float* __restrict__ x,
                            const float* __restrict__ W_enc,
                            const float* __restrict__ b_enc,
                            const float* __restrict__ theta,
                            const float* __restrict__ phi)
{
    __shared__ float partial[256];
    __shared__ float cs[NQ], ss[NQ];
    __shared__ float2 Ush[NL * NQ * 4];

    int b   = blockIdx.x;
    int tid = threadIdx.x;
    int q   = tid & 15;
    int seg = tid >> 4;

    {
        float acc = 0.f;
        const float* xb = x + b * DIN;
        int d0 = seg * 32;
        #pragma unroll 8
        for (int d = d0; d < d0 + 32; d++)
            acc += xb[d] * W_enc[d * NQ + q];
        partial[tid] = acc;
    }
    __syncthreads();
    if (tid < NQ) {
        float s = b_enc[tid];
        #pragma unroll
        for (int g = 0; g < 16; g++) s += partial[g * 16 + tid];
        float ang = tanhf(s) * 3.14159265358979323846f;
        cs[tid] = cosf(0.5f * ang);
        ss[tid] = sinf(0.5f * ang);
    }
    __syncthreads();

    // product tables over amplitude bits (amp bit k -> qubit 15-k)
    {
        int m = tid;
        float p0 = 1.f, p1 = 1.f;
        #pragma unroll
        for (int k = 0; k < 8; k++) {
            int bit = (m >> k) & 1;
            p0 *= bit ? ss[15 - k] : cs[15 - k];
            p1 *= bit ? ss[7 - k]  : cs[7 - k];
        }
        ((float*)g_T0u)[b * 256 + m] = p0;
        g_T1[b * 256 + m] = p1;
    }

    if (b == 0) {
        if (tid < NL * NQ) {
            int l = tid >> 4, qq = tid & 15;
            const float* th = theta + (l * NQ + qq) * 3;
            float a0 = th[0], a1 = th[1], a2 = th[2];
            float ca = cosf(0.5f * a0), sa = sinf(0.5f * a0);
            float cb = cosf(0.5f * a1), sb = sinf(0.5f * a1);
            float cz = cosf(0.5f * a2), sz = sinf(0.5f * a2);
            float2 em = make_float2(cz, -sz);
            float2 ep = make_float2(cz,  sz);
            float2 r00 = make_float2( cb * em.x,  cb * em.y);
            float2 r01 = make_float2(-sb * ep.x, -sb * ep.y);
            float2 r10 = make_float2( sb * em.x,  sb * em.y);
            float2 r11 = make_float2( cb * ep.x,  cb * ep.y);
            float2 u00 = make_float2(ca * r00.x + sa * r10.y, ca * r00.y - sa * r10.x);
            float2 u01 = make_float2(ca * r01.x + sa * r11.y, ca * r01.y - sa * r11.x);
            float2 u10 = make_float2(sa * r00.y + ca * r10.x, -sa * r00.x + ca * r10.y);
            float2 u11 = make_float2(sa * r01.y + ca * r11.x, -sa * r01.x + ca * r11.y);
            int base = tid * 4;
            Ush[base + 0] = u00; Ush[base + 1] = u01;
            Ush[base + 2] = u10; Ush[base + 3] = u11;
        }
        __syncthreads();

        // passA gate constants for qubits 3..14 (g = qubit-3)
        for (int k = tid; k < NL * 144; k += 256) {
            int l = k / 144, rem = k % 144, g = rem / 12, e = rem % 12;
            int j2 = e / 3, kind = e % 3;
            float2 u = Ush[(l * 16 + (g + 3)) * 4 + j2];
            float v = (kind == 0) ? u.x : ((kind == 1) ? u.y : -u.y);
            g_Upk[k] = bc2(v);
        }

        // passB gate constants for qubits 0,1,2 (g = qubit)
        for (int k = tid; k < NL * 36; k += 256) {
            int l = k / 36, rem = k % 36, g = rem / 12, e = rem % 12;
            int j2 = e / 3, kind = e % 3;
            float2 u = Ush[(l * 16 + g) * 4 + j2];
            float v = (kind == 0) ? u.x : ((kind == 1) ? u.y : -u.y);
            g_Bpk[k] = bc2(v);
        }

        // lane gate (qubit 15) packed constants
        if (tid < NL) {
            int l = tid;
            float2 u00 = Ush[(l * 16 + 15) * 4 + 0];
            float2 u01 = Ush[(l * 16 + 15) * 4 + 1];
            float2 u10 = Ush[(l * 16 + 15) * 4 + 2];
            float2 u11 = Ush[(l * 16 + 15) * 4 + 3];
            g_Lq[l * 6 + 0] = pk2(u00.x, u11.x);
            g_Lq[l * 6 + 1] = pk2(u01.x, u10.x);
            g_Lq[l * 6 + 2] = pk2(-u00.y, -u11.y);
            g_Lq[l * 6 + 3] = pk2(-u01.y, -u10.y);
            g_Lq[l * 6 + 4] = pk2(u00.y, u11.y);
            g_Lq[l * 6 + 5] = pk2(u01.y, u10.y);
        }

        // passB diagonal phase tables: edges (0,1),(1,2),(2,3),(15,0)
        // index: [l][s3][j], j bit2 = q0 spin, bit1 = q1, bit0 = q2
        if (tid < NL * 16) {
            int l = tid >> 4, s3i = (tid >> 3) & 1, j = tid & 7;
            float s0 = 1.f - 2.f * ((j >> 2) & 1);
            float s1 = 1.f - 2.f * ((j >> 1) & 1);
            float s2 = 1.f - 2.f * (j & 1);
            float s3 = 1.f - 2.f * (float)s3i;
            const float* ph = phi + l * 16;
            float A = ph[0] * s0 * s1 + ph[1] * s1 * s2 + ph[2] * s2 * s3;
            float C = ph[15] * s0;                     // lane-dependent (s15)
            float a0 = A + C, a1 = A - C;
            float c0, sv0, c1, sv1;
            sincosf(0.5f * a0, &sv0, &c0);
            sincosf(0.5f * a1, &sv1, &c1);
            int o = l * 16 + s3i * 8 + j;
            g_DjRe[o]  = pk2(c0, c1);
            g_DjIm[o]  = pk2(-sv0, -sv1);
            g_DjImN[o] = pk2(sv0, sv1);
        }
    }
}

// ---------------- Pr tables: ZZ edges (3,4)..(13,14) + lane-split edge (14,15) ----------------
__global__ void pr_kernel(const float* __restrict__ phi)
{
    int gid = blockIdx.x * blockDim.x + threadIdx.x;   // NL*4096
    int l = gid >> 12;
    int p = gid & 4095;
    float ang = 0.f;
    #pragma unroll
    for (int bb = 0; bb < 11; bb++) {
        float sA = 1.f - 2.f * ((p >> (bb + 1)) & 1);
        float sB = 1.f - 2.f * ((p >> bb) & 1);
        ang += __ldg(&phi[l * 16 + 13 - bb]) * sA * sB;   // edge (13-bb, 14-bb)
    }
    float e14 = __ldg(&phi[l * 16 + 14]) * (1.f - 2.f * (p & 1));  // edge (14,15)
    float a0 = ang + e14, a1 = ang - e14;
    float c0, s0, c1, s1;
    sincosf(0.5f * a0, &s0, &c0);
    sincosf(0.5f * a1, &s1, &c1);
    g_PrRe[l * 4096 + p]  = pk2(c0, c1);
    g_PrIm[l * 4096 + p]  = pk2(-s0, -s1);
    g_PrImN[l * 4096 + p] = pk2(s0, s1);
}

// ---------------- packed 2x2 gate on 8-value register subcube ----------------
template<int VB>
__device__ __forceinline__ void gate8(ull* ar, ull* ai, const ull* u)
{
    ull u00x = u[0], u00y = u[1],  u00yn = u[2];
    ull u01x = u[3], u01y = u[4],  u01yn = u[5];
    ull u10x = u[6], u10y = u[7],  u10yn = u[8];
    ull u11x = u[9], u11y = u[10], u11yn = u[11];
    #pragma unroll
    for (int m = 0; m < 8; m++) {
        if (m & (1 << VB)) continue;
        int m1 = m | (1 << VB);
        ull axr = ar[m],  axi = ai[m];
        ull bxr = ar[m1], bxi = ai[m1];
        ar[m]  = f2fma(u00x, axr, f2fma(u00yn, axi, f2fma(u01x, bxr, f2mul(u01yn, bxi))));
        ai[m]  = f2fma(u00x, axi, f2fma(u00y,  axr, f2fma(u01x, bxi, f2mul(u01y,  bxr))));
        ar[m1] = f2fma(u10x, axr, f2fma(u10yn, axi, f2fma(u11x, bxr, f2mul(u11yn, bxi))));
        ai[m1] = f2fma(u10x, axi, f2fma(u10y,  axr, f2fma(u11x, bxi, f2mul(u11y,  bxr))));
    }
}

// ---------------- PassA: sweep(lane + q3,q4,q5) + 3 rounds (q6..q14) + Pr ----------------
extern "C" __global__ void __launch_bounds__(512, 2)
passA_kernel(int layer, int init)
{
    extern __shared__ ull smem[];
    ull* sre = smem;           // 4096
    ull* sim = smem + 4096;    // 4096
    __shared__ ull sU[144];
    __shared__ ull sLq[6];

    int t    = threadIdx.x;
    int tile = blockIdx.x;     // p bits 12..14 (qubits 2,1,0)
    int b    = blockIdx.y;
    int base = b * 32768 + tile * 4096;

    if (t < 144) sU[t] = g_Upk[layer * 144 + t];
    if (t < 6)   sLq[t] = g_Lq[layer * 6 + t];
    __syncthreads();

    // ---- load sweep: regs hold u bits 9,10,11 subcube (k = u>>9) ----
    ull vr[8], vi[8];
    if (init) {
        #pragma unroll
        for (int k = 0; k < 8; k++) {
            int u = k * 512 + t;
            int p = (tile << 12) | u;
            float t1 = g_T1[b * 256 + (p >> 7)];
            ull  t0 = g_T0u[b * 128 + (t & 127)];
            vr[k] = f2mul(bc2(t1), t0);
            vi[k] = 0ull;
        }
    } else {
        #pragma unroll
        for (int k = 0; k < 8; k++) {
            vr[k] = g_re[base + k * 512 + t];
            vi[k] = g_im[base + k * 512 + t];
        }
    }

    // lane gate (qubit 15)
    {
        ull P1 = sLq[0], P2 = sLq[1], P3 = sLq[2], P4 = sLq[3], P5 = sLq[4], P6 = sLq[5];
        #pragma unroll
        for (int m = 0; m < 8; m++) {
            ull sar = swap2(vr[m]), sai = swap2(vi[m]);
            ull nr = f2fma(P1, vr[m], f2fma(P2, sar, f2fma(P3, vi[m], f2mul(P4, sai))));
            ull ni = f2fma(P1, vi[m], f2fma(P2, sai, f2fma(P5, vr[m], f2mul(P6, sar))));
            vr[m] = nr; vi[m] = ni;
        }
    }
    // gates on u bits 9,10,11 -> qubits 5,4,3 -> g = 2,1,0
    gate8<0>(vr, vi, &sU[2 * 12]);
    gate8<1>(vr, vi, &sU[1 * 12]);
    gate8<2>(vr, vi, &sU[0]);

    #pragma unroll
    for (int k = 0; k < 8; k++) {
        int s = swz(k * 512 + t);
        sre[s] = vr[k];
        sim[s] = vi[k];
    }

    // ---- 3 smem rounds: u bits {0,1,2},{3,4,5},{6,7,8} ----
    #pragma unroll
    for (int rr = 0; rr < 3; rr++) {
        __syncthreads();
        ull ar[8], ai[8];
        int s  = 3 * rr;
        int lo = t & ((1 << s) - 1);
        int hi = t >> s;
        int pre = (hi << (s + 3)) | lo;
        int idxs[8];
        #pragma unroll
        for (int j = 0; j < 8; j++) idxs[j] = pre | (j << s);

        #pragma unroll
        for (int j = 0; j < 8; j++) {
            int sp = swz(idxs[j]);
            ar[j] = sre[sp];
            ai[j] = sim[sp];
        }

        // u bit (3rr+v) -> qubit 14-(3rr+v) -> g = 11-3rr-v
        gate8<0>(ar, ai, &sU[(11 - 3 * rr) * 12]);
        gate8<1>(ar, ai, &sU[(10 - 3 * rr) * 12]);
        gate8<2>(ar, ai, &sU[( 9 - 3 * rr) * 12]);

        #pragma unroll
        for (int j = 0; j < 8; j++) {
            int sp = swz(idxs[j]);
            sre[sp] = ar[j];
            sim[sp] = ai[j];
        }
    }
    __syncthreads();

    // ---- epilogue: Pr phase + writeout ----
    const ull* PR  = g_PrRe  + layer * 4096;
    const ull* PI  = g_PrIm  + layer * 4096;
    const ull* PIN = g_PrImN + layer * 4096;
    #pragma unroll
    for (int k = 0; k < 8; k++) {
        int u = k * 512 + t;
        int s = swz(u);
        ull re = sre[s], im = sim[s];
        ull cr = PR[u], ci = PI[u], cin = PIN[u];
        ull nre = f2fma(cr, re, f2mul(cin, im));
        ull nim = f2fma(cr, im, f2mul(ci, re));
        g_re[base + u] = nre;
        g_im[base + u] = nim;
    }
}

// ---------------- PassB: butterfly q0,q1,q2 + diag phase (+ expectations) ----------------
extern "C" __global__ void __launch_bounds__(256, 4)
passB_kernel(int layer, int last)
{
    __shared__ ull sG[36];
    __shared__ ull sDR[16], sDI[16], sDIN[16];
    __shared__ float wsum[8][16];

    int t = threadIdx.x;
    int b = blockIdx.y;

    if (t < 36) sG[t] = g_Bpk[layer * 36 + t];
    if (t < 16) {
        sDR[t]  = g_DjRe[layer * 16 + t];
        sDI[t]  = g_DjIm[layer * 16 + t];
        sDIN[t] = g_DjImN[layer * 16 + t];
    }
    __syncthreads();

    int r  = blockIdx.x * 256 + t;     // p bits 0..11
    int s3 = (r >> 11) & 1;            // qubit-3 spin (p bit 11)
    int gb = b * 32768;

    ull ar[8], ai[8];
    #pragma unroll
    for (int j = 0; j < 8; j++) {
        ar[j] = g_re[gb + j * 4096 + r];
        ai[j] = g_im[gb + j * 4096 + r];
    }

    // slab j: bit0 = p bit12 -> q2 (g=2), bit1 -> q1 (g=1), bit2 -> q0 (g=0)
    gate8<0>(ar, ai, &sG[24]);
    gate8<1>(ar, ai, &sG[12]);
    gate8<2>(ar, ai, &sG[0]);

    // diagonal phase: edges (0,1),(1,2),(2,3),(15,0)
    {
        int db = s3 * 8;
        #pragma unroll
        for (int j = 0; j < 8; j++) {
            ull dr = sDR[db + j], di = sDI[db + j], din = sDIN[db + j];
            ull nr = f2fma(dr, ar[j], f2mul(din, ai[j]));
            ai[j]  = f2fma(dr, ai[j], f2mul(di,  ar[j]));
            ar[j]  = nr;
        }
    }

    if (!last) {
        #pragma unroll
        for (int j = 0; j < 8; j++) {
            g_re[gb + j * 4096 + r] = ar[j];
            g_im[gb + j * 4096 + r] = ai[j];
        }
    } else {
        float ptl0 = 0.f, ptl1 = 0.f, a0 = 0.f, a1 = 0.f, a2 = 0.f;
        #pragma unroll
        for (int j = 0; j < 8; j++) {
            ull pp = f2fma(ar[j], ar[j], f2mul(ai[j], ai[j]));
            float l0, l1; up2(pp, l0, l1);
            float pj = l0 + l1;
            ptl0 += l0; ptl1 += l1;
            a0 += ((j >> 2) & 1) ? -pj : pj;   // q0 = slab bit2
            a1 += ((j >> 1) & 1) ? -pj : pj;   // q1 = slab bit1
            a2 += ( j       & 1) ? -pj : pj;   // q2 = slab bit0
        }
        float pt = ptl0 + ptl1;
        float acc[16];
        acc[0] = a0; acc[1] = a1; acc[2] = a2;
        #pragma unroll
        for (int q = 3; q < 15; q++)
            acc[q] = ((r >> (14 - q)) & 1) ? -pt : pt;
        acc[15] = ptl0 - ptl1;

        #pragma unroll
        for (int q = 0; q < 16; q++) {
            float v = acc[q];
            #pragma unroll
            for (int ofs = 16; ofs > 0; ofs >>= 1)
                v += __shfl_down_sync(0xffffffffu, v, ofs);
            if ((t & 31) == 0) wsum[t >> 5][q] = v;
        }
        __syncthreads();
        if (t < 16) {
            float v = 0.f;
            #pragma unroll
            for (int w = 0; w < 8; w++) v += wsum[w][t];
            g_zpart[(b * 16 + blockIdx.x) * 16 + t] = v;
        }
    }
}

// ---------------- final reduce + MLP ----------------
__global__ void final_kernel(const float* __restrict__ W1, const float* __restrict__ b1,
                             const float* __restrict__ W2, const float* __restrict__ b2,
                             float* __restrict__ out)
{
    int t = threadIdx.x;
    int warp = t >> 5, lane = t & 31;
    int b = blockIdx.x * 8 + warp;

    float z = 0.f;
    if (lane < 16) {
        #pragma unroll
        for (int c = 0; c < 16; c++) z += g_zpart[(b * 16 + c) * 16 + lane];
    }
    float h = b1[lane];
    #pragma unroll
    for (int q = 0; q < 16; q++) {
        float zq = __shfl_sync(0xffffffffu, z, q);
        h += zq * W1[q * 32 + lane];
    }
    h = fmaxf(h, 0.f);

    float o = (lane < OUTD) ? b2[lane] : 0.f;
    #pragma unroll
    for (int j = 0; j < 32; j++) {
        float hj = __shfl_sync(0xffffffffu, h, j);
        if (lane < OUTD) o += hj * W2[j * OUTD + lane];
    }
    if (lane < OUTD) out[b * OUTD + lane] = o;
}

// ---------------- launch ----------------
extern "C" void kernel_launch(void* const* d_in, const int* in_sizes, int n_in,
                              void* d_out, int out_size)
{
    const float* x     = (const float*)d_in[0];
    const float* W_enc = (const float*)d_in[1];
    const float* b_enc = (const float*)d_in[2];
    const float* theta = (const float*)d_in[3];
    const float* phi   = (const float*)d_in[4];
    const float* W1    = (const float*)d_in[5];
    const float* b1    = (const float*)d_in[6];
    const float* W2    = (const float*)d_in[7];
    const float* b2    = (const float*)d_in[8];
    float* out = (float*)d_out;

    cudaFuncSetAttribute((const void*)passA_kernel,
                         cudaFuncAttributeMaxDynamicSharedMemorySize, 65536);

    prep_kernel<<<256, 256>>>(x, W_enc, b_enc, theta, phi);
    pr_kernel<<<16, 1024>>>(phi);

    for (int l = 0; l < NL; l++) {
        passA_kernel<<<dim3(8, 256), 512, 65536>>>(l, l == 0 ? 1 : 0);
        passB_kernel<<<dim3(16, 256), 256>>>(l, l == NL - 1 ? 1 : 0);
    }

    final_kernel<<<32, 256>>>(W1, b1, W2, b2, out);
}

// round 11
// speedup vs baseline: 1.3144x; 1.1663x over previous
#include <cuda_runtime.h>
#include <math.h>

#define NQ       16
#define BATCH    256
#define NL       4
#define DIN      512
#define OUTD     10

typedef unsigned long long ull;

// ---------------- scratch (SoA state, packed across amp bit 0 = qubit 15) ----------------
__device__ ull   g_re[BATCH * 32768];        // 64 MB re pairs
__device__ ull   g_im[BATCH * 32768];        // 64 MB im pairs
__device__ ull   g_T0u[BATCH * 128];
__device__ float g_T1[BATCH * 256];
__device__ ull   g_Rnd[NL * 9 * 12];         // round gates: [l][ubit 0..8] -> qubit 14-ubit
__device__ ull   g_OwnCk[NL * 3 * 12];       // own chunk gates: [pi][kbit]
__device__ ull   g_Def[NL * 3 * 12];         // deferred gates: [slot=layer][kbit]
__device__ ull   g_Lane[NL * 6];             // lane (q15) gate consts
__device__ ull   g_PrRe[NL * 4096], g_PrIm[NL * 4096], g_PrImN[NL * 4096];  // covA epilogue diag
__device__ ull   g_LBRe[512], g_LBIm[512], g_LBImN[512];   // covB epi low (layer 1)
__device__ ull   g_TBRe[8],   g_TBIm[8],   g_TBImN[8];     // covB epi k-part (layer 1)
__device__ ull   g_DjBRe[2*16], g_DjBIm[2*16], g_DjBImN[2*16];  // covB chunk diag [l/2][s3][k] layers 0,2
__device__ ull   g_DjARe[32],  g_DjAIm[32],  g_DjAImN[32];      // covA chunk diag [k][q2b][t8] layer 1
__device__ float g_zpart[BATCH * 8 * 16];

// ---------------- f32x2 helpers ----------------
__device__ __forceinline__ ull pk2(float lo, float hi) {
    ull r; asm("mov.b64 %0, {%1, %2};" : "=l"(r) : "f"(lo), "f"(hi)); return r;
}
__device__ __forceinline__ ull bc2(float v) {
    ull r; asm("mov.b64 %0, {%1, %1};" : "=l"(r) : "f"(v)); return r;
}
__device__ __forceinline__ void up2(ull v, float& lo, float& hi) {
    asm("mov.b64 {%0, %1}, %2;" : "=f"(lo), "=f"(hi) : "l"(v));
}
__device__ __forceinline__ ull f2fma(ull a, ull b, ull c) {
    ull d; asm("fma.rn.f32x2 %0, %1, %2, %3;" : "=l"(d) : "l"(a), "l"(b), "l"(c)); return d;
}
__device__ __forceinline__ ull f2mul(ull a, ull b) {
    ull d; asm("mul.rn.f32x2 %0, %1, %2;" : "=l"(d) : "l"(a), "l"(b)); return d;
}
__device__ __forceinline__ ull swap2(ull v) {
    float lo, hi; up2(v, lo, hi); return pk2(hi, lo);
}
__device__ __forceinline__ int swz(int i) { return i ^ ((i >> 3) & 15); }

// ---------------- prep ----------------
__global__ void prep_kernel(const float* __restrict__ x,
                            const float* __restrict__ W_enc,
                            const float* __restrict__ b_enc,
                            const float* __restrict__ theta)
{
    __shared__ float partial[256];
    __shared__ float cs[NQ], ss[NQ];
    __shared__ float2 Ush[NL * NQ * 4];

    int b   = blockIdx.x;
    int tid = threadIdx.x;
    int q   = tid & 15;
    int seg = tid >> 4;

    {
        float acc = 0.f;
        const float* xb = x + b * DIN;
        int d0 = seg * 32;
        #pragma unroll 8
        for (int d = d0; d < d0 + 32; d++)
            acc += xb[d] * W_enc[d * NQ + q];
        partial[tid] = acc;
    }
    __syncthreads();
    if (tid < NQ) {
        float s = b_enc[tid];
        #pragma unroll
        for (int g = 0; g < 16; g++) s += partial[g * 16 + tid];
        float ang = tanhf(s) * 3.14159265358979323846f;
        cs[tid] = cosf(0.5f * ang);
        ss[tid] = sinf(0.5f * ang);
    }
    __syncthreads();

    // product tables over amplitude bits (amp bit k -> qubit 15-k)
    {
        int m = tid;
        float p0 = 1.f, p1 = 1.f;
        #pragma unroll
        for (int k = 0; k < 8; k++) {
            int bit = (m >> k) & 1;
            p0 *= bit ? ss[15 - k] : cs[15 - k];
            p1 *= bit ? ss[7 - k]  : cs[7 - k];
        }
        ((float*)g_T0u)[b * 256 + m] = p0;
        g_T1[b * 256 + m] = p1;
    }

    if (b == 0) {
        if (tid < NL * NQ) {
            int l = tid >> 4, qq = tid & 15;
            const float* th = theta + (l * NQ + qq) * 3;
            float a0 = th[0], a1 = th[1], a2 = th[2];
            float ca = cosf(0.5f * a0), sa = sinf(0.5f * a0);
            float cb = cosf(0.5f * a1), sb = sinf(0.5f * a1);
            float cz = cosf(0.5f * a2), sz = sinf(0.5f * a2);
            float2 em = make_float2(cz, -sz);
            float2 ep = make_float2(cz,  sz);
            float2 r00 = make_float2( cb * em.x,  cb * em.y);
            float2 r01 = make_float2(-sb * ep.x, -sb * ep.y);
            float2 r10 = make_float2( sb * em.x,  sb * em.y);
            float2 r11 = make_float2( cb * ep.x,  cb * ep.y);
            float2 u00 = make_float2(ca * r00.x + sa * r10.y, ca * r00.y - sa * r10.x);
            float2 u01 = make_float2(ca * r01.x + sa * r11.y, ca * r01.y - sa * r11.x);
            float2 u10 = make_float2(sa * r00.y + ca * r10.x, -sa * r00.x + ca * r10.y);
            float2 u11 = make_float2(sa * r01.y + ca * r11.x, -sa * r01.x + ca * r11.y);
            int base = tid * 4;
            Ush[base + 0] = u00; Ush[base + 1] = u01;
            Ush[base + 2] = u10; Ush[base + 3] = u11;
        }
        __syncthreads();

        // round gates: [l][ubit][12], ubit 0..8 -> qubit 14-ubit
        for (int k = tid; k < NL * 108; k += 256) {
            int l = k / 108, rem = k % 108, ub = rem / 12, e = rem % 12;
            int j2 = e / 3, kind = e % 3;
            float2 u = Ush[(l * 16 + (14 - ub)) * 4 + j2];
            float v = (kind == 0) ? u.x : ((kind == 1) ? u.y : -u.y);
            g_Rnd[k] = bc2(v);
        }
        // own chunk gates: [pi][kbit][12]; covA(pi even): q = 5-kbit; covB: q = 2-kbit
        for (int k = tid; k < NL * 36; k += 256) {
            int pi = k / 36, rem = k % 36, kb = rem / 12, e = rem % 12;
            int qq = ((pi & 1) ? 2 : 5) - kb;
            int j2 = e / 3, kind = e % 3;
            float2 u = Ush[(pi * 16 + qq) * 4 + j2];
            float v = (kind == 0) ? u.x : ((kind == 1) ? u.y : -u.y);
            g_OwnCk[k] = bc2(v);
        }
        // deferred gates: [slot=s][kbit][12]; s even: q = 2-kbit; s odd: q = 5-kbit
        for (int k = tid; k < NL * 36; k += 256) {
            int s = k / 36, rem = k % 36, kb = rem / 12, e = rem % 12;
            int qq = ((s & 1) ? 5 : 2) - kb;
            int j2 = e / 3, kind = e % 3;
            float2 u = Ush[(s * 16 + qq) * 4 + j2];
            float v = (kind == 0) ? u.x : ((kind == 1) ? u.y : -u.y);
            g_Def[k] = bc2(v);
        }
        // lane gate (qubit 15)
        if (tid < NL) {
            int l = tid;
            float2 u00 = Ush[(l * 16 + 15) * 4 + 0];
            float2 u01 = Ush[(l * 16 + 15) * 4 + 1];
            float2 u10 = Ush[(l * 16 + 15) * 4 + 2];
            float2 u11 = Ush[(l * 16 + 15) * 4 + 3];
            g_Lane[l * 6 + 0] = pk2(u00.x, u11.x);
            g_Lane[l * 6 + 1] = pk2(u01.x, u10.x);
            g_Lane[l * 6 + 2] = pk2(-u00.y, -u11.y);
            g_Lane[l * 6 + 3] = pk2(-u01.y, -u10.y);
            g_Lane[l * 6 + 4] = pk2(u00.y, u11.y);
            g_Lane[l * 6 + 5] = pk2(u01.y, u10.y);
        }
    }
}

// ---------------- PrA: covA epilogue diag (edges (3,4)..(13,14) + (14,15)) ----------------
__global__ void pr_kernel(const float* __restrict__ phi)
{
    int gid = blockIdx.x * blockDim.x + threadIdx.x;   // NL*4096
    int l = gid >> 12;
    int p = gid & 4095;
    float ang = 0.f;
    #pragma unroll
    for (int bb = 0; bb < 11; bb++) {
        float sA = 1.f - 2.f * ((p >> (bb + 1)) & 1);
        float sB = 1.f - 2.f * ((p >> bb) & 1);
        ang += __ldg(&phi[l * 16 + 13 - bb]) * sA * sB;
    }
    float e14 = __ldg(&phi[l * 16 + 14]) * (1.f - 2.f * (p & 1));
    float a0 = ang + e14, a1 = ang - e14;
    float c0, s0, c1, s1;
    sincosf(0.5f * a0, &s0, &c0);
    sincosf(0.5f * a1, &s1, &c1);
    g_PrRe[l * 4096 + p]  = pk2(c0, c1);
    g_PrIm[l * 4096 + p]  = pk2(-s0, -s1);
    g_PrImN[l * 4096 + p] = pk2(s0, s1);
}

// ---------------- small diag tables: LB/TB (layer1 epi), DjB (layers 0,2), DjA (layer 1) ----------------
__global__ void tbl_kernel(const float* __restrict__ phi)
{
    int gid = blockIdx.x * 512 + threadIdx.x;
    if (gid < 512) {
        // LB[t]: edges (6,7)..(13,14) over t bits + (14,15) lane-split; layer 1
        int t = gid;
        float ang = 0.f;
        #pragma unroll
        for (int bb = 0; bb < 8; bb++) {
            float sA = 1.f - 2.f * ((t >> (bb + 1)) & 1);
            float sB = 1.f - 2.f * ((t >> bb) & 1);
            ang += __ldg(&phi[16 + 13 - bb]) * sA * sB;
        }
        float C = __ldg(&phi[16 + 14]) * (1.f - 2.f * (t & 1));
        float a0 = ang + C, a1 = ang - C;
        float c0, s0, c1, s1;
        sincosf(0.5f * a0, &s0, &c0);
        sincosf(0.5f * a1, &s1, &c1);
        g_LBRe[t]  = pk2(c0, c1);
        g_LBIm[t]  = pk2(-s0, -s1);
        g_LBImN[t] = pk2(s0, s1);
    } else if (gid < 520) {
        // TB[k]: edges (0,1),(1,2) + (15,0) lane; layer 1; k bit2=q0,bit1=q1,bit0=q2
        int k = gid - 512;
        float s0v = 1.f - 2.f * ((k >> 2) & 1);
        float s1v = 1.f - 2.f * ((k >> 1) & 1);
        float s2v = 1.f - 2.f * (k & 1);
        float ang = __ldg(&phi[16 + 0]) * s0v * s1v + __ldg(&phi[16 + 1]) * s1v * s2v;
        float C = __ldg(&phi[16 + 15]) * s0v;
        float a0 = ang + C, a1 = ang - C;
        float c0, s0, c1, s1;
        sincosf(0.5f * a0, &s0, &c0);
        sincosf(0.5f * a1, &s1, &c1);
        g_TBRe[k]  = pk2(c0, c1);
        g_TBIm[k]  = pk2(-s0, -s1);
        g_TBImN[k] = pk2(s0, s1);
    } else if (gid < 552) {
        // DjB[lh][s3][k]: edges (0,1),(1,2),(2,3),(15,0); lh=0 -> layer0, lh=1 -> layer2
        int i = gid - 520;
        int lh = i >> 4, l = lh * 2, s3i = (i >> 3) & 1, k = i & 7;
        float s0v = 1.f - 2.f * ((k >> 2) & 1);
        float s1v = 1.f - 2.f * ((k >> 1) & 1);
        float s2v = 1.f - 2.f * (k & 1);
        float s3v = 1.f - 2.f * (float)s3i;
        const float* ph = phi + l * 16;
        float ang = __ldg(&ph[0]) * s0v * s1v + __ldg(&ph[1]) * s1v * s2v + __ldg(&ph[2]) * s2v * s3v;
        float C = __ldg(&ph[15]) * s0v;
        float a0 = ang + C, a1 = ang - C;
        float c0, s0, c1, s1;
        sincosf(0.5f * a0, &s0, &c0);
        sincosf(0.5f * a1, &s1, &c1);
        g_DjBRe[i]  = pk2(c0, c1);
        g_DjBIm[i]  = pk2(-s0, -s1);
        g_DjBImN[i] = pk2(s0, s1);
    } else if (gid < 584) {
        // DjA[k][q2b][t8]: edges (2,3),(3,4),(4,5),(5,6); layer 1; k bit2=q3,bit1=q4,bit0=q5
        int i = gid - 552;
        int k = i >> 2, q2b = (i >> 1) & 1, t8 = i & 1;
        float s3v = 1.f - 2.f * ((k >> 2) & 1);
        float s4v = 1.f - 2.f * ((k >> 1) & 1);
        float s5v = 1.f - 2.f * (k & 1);
        float s2v = 1.f - 2.f * (float)q2b;
        float s6v = 1.f - 2.f * (float)t8;
        const float* ph = phi + 16;
        float ang = __ldg(&ph[2]) * s2v * s3v + __ldg(&ph[3]) * s3v * s4v
                  + __ldg(&ph[4]) * s4v * s5v + __ldg(&ph[5]) * s5v * s6v;
        float c0, s0;
        sincosf(0.5f * ang, &s0, &c0);
        g_DjARe[i]  = bc2(c0);
        g_DjAIm[i]  = bc2(-s0);
        g_DjAImN[i] = bc2(s0);
    }
}

// ---------------- packed 2x2 gate on 8-value register subcube ----------------
template<int VB>
__device__ __forceinline__ void gate8(ull* ar, ull* ai, const ull* u)
{
    ull u00x = u[0], u00y = u[1],  u00yn = u[2];
    ull u01x = u[3], u01y = u[4],  u01yn = u[5];
    ull u10x = u[6], u10y = u[7],  u10yn = u[8];
    ull u11x = u[9], u11y = u[10], u11yn = u[11];
    #pragma unroll
    for (int m = 0; m < 8; m++) {
        if (m & (1 << VB)) continue;
        int m1 = m | (1 << VB);
        ull axr = ar[m],  axi = ai[m];
        ull bxr = ar[m1], bxi = ai[m1];
        ar[m]  = f2fma(u00x, axr, f2fma(u00yn, axi, f2fma(u01x, bxr, f2mul(u01yn, bxi))));
        ai[m]  = f2fma(u00x, axi, f2fma(u00y,  axr, f2fma(u01x, bxi, f2mul(u01y,  bxr))));
        ar[m1] = f2fma(u10x, axr, f2fma(u10yn, axi, f2fma(u11x, bxr, f2mul(u11yn, bxi))));
        ai[m1] = f2fma(u10x, axi, f2fma(u10y,  axr, f2fma(u11x, bxi, f2mul(u11y,  bxr))));
    }
}

// ---------------- unified pass kernel (pi = 0..4) ----------------
extern "C" __global__ void __launch_bounds__(512, 2)
pass_kernel(int pi)
{
    extern __shared__ ull smem[];           // 4096 + 4096 (passes 0..3 only)
    ull* sre = smem;
    ull* sim = smem + 4096;
    __shared__ ull sR[108];
    __shared__ ull sCk[36], sDf[36], sLn[6];
    __shared__ ull sDjR[16], sDjI[16], sDjN[16];
    __shared__ float wsum[16][16];

    const int t    = threadIdx.x;
    const int tile = blockIdx.x;            // 3 block bits
    const int b    = blockIdx.y;
    const bool covB = (pi == 1 || pi == 3);
    const bool fin  = (pi == 4);
    // covA: base + k*512 + t ; covB: base + k*4096 + t
    const int base = b * 32768 + (covB ? (tile << 9) : (tile << 12));
    const int kstr = covB ? 4096 : 512;

    if (!fin) {
        if (t < 108) sR[t] = g_Rnd[pi * 108 + t];
        if (t >= 128 && t < 164) sCk[t - 128] = g_OwnCk[pi * 36 + (t - 128)];
        if (t >= 192 && t < 198) sLn[t - 192] = g_Lane[pi * 6 + (t - 192)];
    }
    if (pi > 0) {
        if (t >= 224 && t < 260) sDf[t - 224] = g_Def[(pi - 1) * 36 + (t - 224)];
        if (pi == 1 || pi == 3) {
            int s3 = (tile >> 2) & 1, lh = (pi - 1) >> 1;
            if (t >= 288 && t < 296)
                { int k = t - 288; sDjR[k] = g_DjBRe[lh*16 + s3*8 + k];
                  sDjI[k] = g_DjBIm[lh*16 + s3*8 + k]; sDjN[k] = g_DjBImN[lh*16 + s3*8 + k]; }
        } else if (pi == 2) {
            int q2b = tile & 1;
            if (t >= 288 && t < 304)
                { int i = t - 288; int k = i >> 1, t8 = i & 1;
                  int gi = k*4 + q2b*2 + t8;
                  sDjR[i] = g_DjARe[gi]; sDjI[i] = g_DjAIm[gi]; sDjN[i] = g_DjAImN[gi]; }
        }
    }
    __syncthreads();

    // ---- chunk phase: registers hold the 8 k-slabs ----
    ull vr[8], vi[8];
    if (pi == 0) {
        #pragma unroll
        for (int k = 0; k < 8; k++) {
            int p = (tile << 12) | (k << 9) | t;
            float t1 = g_T1[b * 256 + (p >> 7)];
            ull  t0 = g_T0u[b * 128 + (t & 127)];
            vr[k] = f2mul(bc2(t1), t0);
            vi[k] = 0ull;
        }
    } else {
        #pragma unroll
        for (int k = 0; k < 8; k++) {
            vr[k] = g_re[base + k * kstr + t];
            vi[k] = g_im[base + k * kstr + t];
        }
        // deferred gates from layer pi-1 (on k bits)
        gate8<0>(vr, vi, &sDf[0]);
        gate8<1>(vr, vi, &sDf[12]);
        gate8<2>(vr, vi, &sDf[24]);
        // deferred diagonal
        if (pi == 1 || pi == 3) {
            #pragma unroll
            for (int k = 0; k < 8; k++) {
                ull cr = sDjR[k], ci = sDjI[k], cin = sDjN[k];
                ull nr = f2fma(cr, vr[k], f2mul(cin, vi[k]));
                vi[k]  = f2fma(cr, vi[k], f2mul(ci,  vr[k]));
                vr[k]  = nr;
            }
        } else if (pi == 2) {
            int t8 = (t >> 8) & 1;
            #pragma unroll
            for (int k = 0; k < 8; k++) {
                int i = k * 2 + t8;
                ull cr = sDjR[i], ci = sDjI[i], cin = sDjN[i];
                ull nr = f2fma(cr, vr[k], f2mul(cin, vi[k]));
                vi[k]  = f2fma(cr, vi[k], f2mul(ci,  vr[k]));
                vr[k]  = nr;
            }
        }
    }

    if (fin) {
        // ---- expectations (no diag needed; layer-3 diagonal unobservable) ----
        float ptl0 = 0.f, ptl1 = 0.f, a3 = 0.f, a4 = 0.f, a5 = 0.f;
        #pragma unroll
        for (int k = 0; k < 8; k++) {
            ull pp = f2fma(vr[k], vr[k], f2mul(vi[k], vi[k]));
            float l0, l1; up2(pp, l0, l1);
            float pj = l0 + l1;
            ptl0 += l0; ptl1 += l1;
            a3 += ((k >> 2) & 1) ? -pj : pj;   // q3 = k bit2
            a4 += ((k >> 1) & 1) ? -pj : pj;   // q4 = k bit1
            a5 += ( k       & 1) ? -pj : pj;   // q5 = k bit0
        }
        float pt = ptl0 + ptl1;
        float acc[16];
        acc[0] = ((tile >> 2) & 1) ? -pt : pt;   // q0 = p14 = tile bit2
        acc[1] = ((tile >> 1) & 1) ? -pt : pt;   // q1 = tile bit1
        acc[2] = ( tile       & 1) ? -pt : pt;   // q2 = tile bit0
        acc[3] = a3; acc[4] = a4; acc[5] = a5;
        #pragma unroll
        for (int q = 6; q < 15; q++)
            acc[q] = ((t >> (14 - q)) & 1) ? -pt : pt;   // q = 14-k <-> t bit k
        acc[15] = ptl0 - ptl1;

        #pragma unroll
        for (int q = 0; q < 16; q++) {
            float v = acc[q];
            #pragma unroll
            for (int o = 16; o > 0; o >>= 1)
                v += __shfl_down_sync(0xffffffffu, v, o);
            if ((t & 31) == 0) wsum[t >> 5][q] = v;
        }
        __syncthreads();
        if (t < 16) {
            float v = 0.f;
            #pragma unroll
            for (int w = 0; w < 16; w++) v += wsum[w][t];
            g_zpart[(b * 8 + tile) * 16 + t] = v;
        }
        return;
    }

    // ---- own layer: lane gate + chunk gates, then write to smem ----
    {
        ull P1 = sLn[0], P2 = sLn[1], P3 = sLn[2], P4 = sLn[3], P5 = sLn[4], P6 = sLn[5];
        #pragma unroll
        for (int m = 0; m < 8; m++) {
            ull sar = swap2(vr[m]), sai = swap2(vi[m]);
            ull nr = f2fma(P1, vr[m], f2fma(P2, sar, f2fma(P3, vi[m], f2mul(P4, sai))));
            ull ni = f2fma(P1, vi[m], f2fma(P2, sai, f2fma(P5, vr[m], f2mul(P6, sar))));
            vr[m] = nr; vi[m] = ni;
        }
    }
    gate8<0>(vr, vi, &sCk[0]);
    gate8<1>(vr, vi, &sCk[12]);
    gate8<2>(vr, vi, &sCk[24]);

    #pragma unroll
    for (int k = 0; k < 8; k++) {
        int s = swz(k * 512 + t);
        sre[s] = vr[k];
        sim[s] = vi[k];
    }

    // ---- 3 smem rounds: u bits {0,1,2},{3,4,5},{6,7,8} -> qubits 14..6 ----
    #pragma unroll
    for (int rr = 0; rr < 3; rr++) {
        __syncthreads();
        ull ar[8], ai[8];
        int s  = 3 * rr;
        int lo = t & ((1 << s) - 1);
        int hi = t >> s;
        int pre = (hi << (s + 3)) | lo;
        int idxs[8];
        #pragma unroll
        for (int j = 0; j < 8; j++) idxs[j] = pre | (j << s);

        #pragma unroll
        for (int j = 0; j < 8; j++) {
            int sp = swz(idxs[j]);
            ar[j] = sre[sp];
            ai[j] = sim[sp];
        }

        gate8<0>(ar, ai, &sR[(3 * rr + 0) * 12]);
        gate8<1>(ar, ai, &sR[(3 * rr + 1) * 12]);
        gate8<2>(ar, ai, &sR[(3 * rr + 2) * 12]);

        #pragma unroll
        for (int j = 0; j < 8; j++) {
            int sp = swz(idxs[j]);
            sre[sp] = ar[j];
            sim[sp] = ai[j];
        }
    }
    __syncthreads();

    // ---- epilogue diag + store sweep ----
    if (pi == 0 || pi == 2) {
        const ull* PR  = g_PrRe  + pi * 4096;
        const ull* PI  = g_PrIm  + pi * 4096;
        const ull* PIN = g_PrImN + pi * 4096;
        #pragma unroll
        for (int k = 0; k < 8; k++) {
            int u = k * 512 + t;
            int s = swz(u);
            ull re = sre[s], im = sim[s];
            ull cr = PR[u], ci = PI[u], cin = PIN[u];
            ull nre = f2fma(cr, re, f2mul(cin, im));
            ull nim = f2fma(cr, im, f2mul(ci, re));
            g_re[base + k * kstr + t] = nre;
            g_im[base + k * kstr + t] = nim;
        }
    } else if (pi == 1) {
        ull lbR = g_LBRe[t], lbI = g_LBIm[t], lbIN = g_LBImN[t];
        #pragma unroll
        for (int k = 0; k < 8; k++) {
            ull tbR = g_TBRe[k], tbI = g_TBIm[k], tbIN = g_TBImN[k];
            ull cR  = f2fma(lbIN, tbI, f2mul(lbR, tbR));
            ull cI  = f2fma(lbR, tbI, f2mul(lbI, tbR));
            ull cIN = f2fma(lbR, tbIN, f2mul(lbIN, tbR));
            int s = swz(k * 512 + t);
            ull re = sre[s], im = sim[s];
            ull nre = f2fma(cR, re, f2mul(cIN, im));
            ull nim = f2fma(cR, im, f2mul(cI, re));
            g_re[base + k * kstr + t] = nre;
            g_im[base + k * kstr + t] = nim;
        }
    } else {  // pi == 3: layer-3 partial diagonal is unobservable -> skip
        #pragma unroll
        for (int k = 0; k < 8; k++) {
            int s = swz(k * 512 + t);
            g_re[base + k * kstr + t] = sre[s];
            g_im[base + k * kstr + t] = sim[s];
        }
    }
}

// ---------------- final reduce + MLP ----------------
__global__ void final_kernel(const float* __restrict__ W1, const float* __restrict__ b1,
                             const float* __restrict__ W2, const float* __restrict__ b2,
                             float* __restrict__ out)
{
    int t = threadIdx.x;
    int warp = t >> 5, lane = t & 31;
    int b = blockIdx.x * 8 + warp;

    float z = 0.f;
    if (lane < 16) {
        #pragma unroll
        for (int c = 0; c < 8; c++) z += g_zpart[(b * 8 + c) * 16 + lane];
    }
    float h = b1[lane];
    #pragma unroll
    for (int q = 0; q < 16; q++) {
        float zq = __shfl_sync(0xffffffffu, z, q);
        h += zq * W1[q * 32 + lane];
    }
    h = fmaxf(h, 0.f);

    float o = (lane < OUTD) ? b2[lane] : 0.f;
    #pragma unroll
    for (int j = 0; j < 32; j++) {
        float hj = __shfl_sync(0xffffffffu, h, j);
        if (lane < OUTD) o += hj * W2[j * OUTD + lane];
    }
    if (lane < OUTD) out[b * OUTD + lane] = o;
}

// ---------------- launch ----------------
extern "C" void kernel_launch(void* const* d_in, const int* in_sizes, int n_in,
                              void* d_out, int out_size)
{
    const float* x     = (const float*)d_in[0];
    const float* W_enc = (const float*)d_in[1];
    const float* b_enc = (const float*)d_in[2];
    const float* theta = (const float*)d_in[3];
    const float* phi   = (const float*)d_in[4];
    const float* W1    = (const float*)d_in[5];
    const float* b1    = (const float*)d_in[6];
    const float* W2    = (const float*)d_in[7];
    const float* b2    = (const float*)d_in[8];
    float* out = (float*)d_out;

    cudaFuncSetAttribute((const void*)pass_kernel,
                         cudaFuncAttributeMaxDynamicSharedMemorySize, 65536);

    prep_kernel<<<256, 256>>>(x, W_enc, b_enc, theta);
    pr_kernel<<<16, 1024>>>(phi);
    tbl_kernel<<<2, 512>>>(phi);

    for (int pi = 0; pi < 5; pi++)
        pass_kernel<<<dim3(8, 256), 512, (pi == 4) ? 0 : 65536>>>(pi);

    final_kernel<<<32, 256>>>(W1, b1, W2, b2, out);
}